// round 16
// baseline (speedup 1.0000x reference)
#include <cuda_runtime.h>

// XrayTransforms: standardize -> soft-hist equalize -> 2x bilinear (=2x2 avg) -> normalize
// x: (2,1,512,512) f32, out: (2,1,256,256) f32
//
// Round 16: 3 kernels, single input pass for stats.
//   k_hist      : minmax partials + fixed-grid fine hist of RAW x (2048 bins
//                 over [0,1)), atomic flush to g_mom
//   k_convtable : reduce minmax -> scale; Gaussian conv on the runtime-mapped
//                 grid (8 taps/lane); scan -> cdfn; eq table (4096)
//   k_out       : table lerp + 2x2 avg + normalize; re-zeroes g_mom for the
//                 next graph replay (device globals start zero)

#define NB 256
#define HW 512
#define NPIX (HW*HW)            // 262144 per batch
#define SUBN 2048
#define TABN 4096
#define RADIUS 12
#define TWO_A_D  39.21568627450980f   // 2*A*Delta (Delta = 1/255), A = 5000
#define A_D2     0.07689350249903883f // A*Delta^2
#define RATIO_C  0.85745500f          // exp(-2*A*Delta^2)
#define INV255   (1.0f/255.0f)
#define LPAD 128
#define PWIN 2336               // 128 + 2048 + 160 (need up to 2176+128=2304)
#define PAD (NB + 2*RADIUS)     // 280

__device__ float g_pmin[128];
__device__ float g_pmax[128];
__device__ float g_scale[2];            // [0]=min, [1]=1/(max-min+1e-6)
__device__ float g_mom[2][SUBN];        // fine hist of raw x (atomic-accumulated)
__device__ float g_eqtab[2][TABN + 4];  // +guard

// grid (64,2) x 512: one input pass: minmax partials + fixed-grid binning.
__global__ void __launch_bounds__(512)
k_hist(const float* __restrict__ x) {
    __shared__ float sh[SUBN];                 // 8KB
    __shared__ float smn[512], smx[512];       // 4KB
    const int t = threadIdx.x;
    const int b = blockIdx.y;

    for (int i = t; i < SUBN; i += 512) sh[i] = 0.0f;

    const float4* xb = (const float4*)(x + b * NPIX) + blockIdx.x * 1024;
    float4 p0 = xb[t];
    float4 p1 = xb[512 + t];
    __syncthreads();

    // min/max over this thread's 8 px
    float mn = fminf(fminf(p0.x, p0.y), fminf(p0.z, p0.w));
    float mx = fmaxf(fmaxf(p0.x, p0.y), fmaxf(p0.z, p0.w));
    mn = fminf(mn, fminf(fminf(p1.x, p1.y), fminf(p1.z, p1.w)));
    mx = fmaxf(mx, fmaxf(fmaxf(p1.x, p1.y), fmaxf(p1.z, p1.w)));
    smn[t] = mn; smx[t] = mx;

    // fixed-grid binning of raw x: bin i = floor(x*2048), centers (i+0.5)/2048
    float vv[8] = {p0.x, p0.y, p0.z, p0.w, p1.x, p1.y, p1.z, p1.w};
    #pragma unroll
    for (int q = 0; q < 8; q++) {
        int i = (int)(vv[q] * 2048.0f);
        i = min(max(i, 0), SUBN - 1);
        atomicAdd(&sh[i], 1.0f);
    }
    __syncthreads();

    for (int o = 256; o; o >>= 1) {
        if (t < o) {
            smn[t] = fminf(smn[t], smn[t + o]);
            smx[t] = fmaxf(smx[t], smx[t + o]);
        }
        __syncthreads();
    }
    if (t == 0) {
        int bid = b * 64 + blockIdx.x;
        g_pmin[bid] = smn[0];
        g_pmax[bid] = smx[0];
    }

    // counts are exact integers in f32 -> order-independent, deterministic
    float* dst = g_mom[b];
    for (int i = t; i < SUBN; i += 512) {
        float v = sh[i];
        if (v != 0.0f) atomicAdd(&dst[i], v);
    }
}

// grid (8,2) x 512: reduce minmax; runtime-grid conv; scan; eq table.
__global__ void __launch_bounds__(512)
k_convtable() {
    __shared__ float win[PWIN];
    __shared__ float SC[NB];
    __shared__ float CP[PAD];
    __shared__ float MP[PAD];
    __shared__ float smm[128];
    __shared__ float s_mn, s_range;
    const int b = blockIdx.y;
    const int t = threadIdx.x;          // 512 threads = 16 warps
    const int wid = t >> 5;
    const int lane = t & 31;

    // reduce 128 minmax partials (redundant per block)
    if (t < 128) smm[t] = g_pmin[t];
    __syncthreads();
    for (int o = 64; o; o >>= 1) { if (t < o) smm[t] = fminf(smm[t], smm[t + o]); __syncthreads(); }
    if (t == 0) s_mn = smm[0];
    __syncthreads();
    if (t < 128) smm[t] = g_pmax[t];
    __syncthreads();
    for (int o = 64; o; o >>= 1) { if (t < o) smm[t] = fmaxf(smm[t], smm[t + o]); __syncthreads(); }
    if (t == 0) {
        s_range = smm[0] - s_mn + 1e-6f;
        if (blockIdx.x == 0 && b == 0) {
            g_scale[0] = s_mn;
            g_scale[1] = 1.0f / s_range;
        }
    }

    for (int i = t; i < PWIN; i += 512) {
        int gi = i - LPAD;
        win[i] = (gi >= 0 && gi < SUBN) ? g_mom[b][gi] : 0.0f;
    }
    if (t < PAD) { CP[t] = 0.0f; MP[t] = 0.0f; }
    __syncthreads();

    const float mn    = s_mn;
    const float range = s_range;
    const float inv   = 1.0f / range;
    const float s     = inv * (1.0f / 2048.0f);   // v-spacing of fine bins
    const float dlt   = 32.0f * s;
    const float rstep = __expf(-10000.0f * dlt * dlt);   // exp(-2*A*dlt^2)

    // conv: warp per bin; lane taps m = lane-127 + 32*it, 8 taps (covers -127..128)
    #pragma unroll
    for (int jj = 0; jj < 16; jj++) {
        const int j = wid * 16 + jj;                 // bin 0..255
        float bj = (float)j * INV255;
        float icen = (bj * range + mn) * 2048.0f - 0.5f;   // fine-bin index of b_j
        int i0 = __float2int_rn(icen);
        float d0 = ((float)i0 - icen + (float)(lane - 127)) * s;
        float w = __expf(-5000.0f * d0 * d0);
        float r = __expf(-5000.0f * (2.0f * d0 * dlt + dlt * dlt));
        const float* p = win + LPAD + i0 + (lane - 127);
        float h = 0.0f;
        #pragma unroll
        for (int it = 0; it < 8; it++) {
            h += w * p[it * 32];
            w *= r;
            r *= rstep;
        }
        #pragma unroll
        for (int o = 16; o; o >>= 1) h += __shfl_xor_sync(0xFFFFFFFFu, h, o);
        if (lane == 0) SC[j] = h;
    }
    __syncthreads();

    #pragma unroll
    for (int o = 1; o < NB; o <<= 1) {
        float add = (t < NB && t >= o) ? SC[t - o] : 0.0f;
        __syncthreads();
        if (t < NB) SC[t] += add;
        __syncthreads();
    }
    if (t < NB) {
        float total = SC[NB - 1];
        float invS  = 1.0f / (total + 1e-10f);
        float cdf   = SC[t] * invS;
        float cdf0  = SC[0] * invS;
        CP[t + RADIUS] = (cdf - cdf0) / (1.0f - cdf0 + 1e-10f);
        MP[t + RADIUS] = 1.0f;
    }
    __syncthreads();

    int p = blockIdx.x * 512 + t;       // 0..TABN-1
    float v = (float)p * (1.0f / (float)(TABN - 1));
    int k = __float2int_rn(v * 255.0f);
    int jlo = k - RADIUS;
    float d0 = v - (float)jlo * INV255;
    float w = __expf(-5000.0f * d0 * d0);
    float r = __expf(TWO_A_D * d0 - A_D2);
    const float* cpp = CP + jlo + RADIUS;
    const float* mpp = MP + jlo + RADIUS;
    float num = 0.0f, den = 0.0f;
    #pragma unroll
    for (int st = 0; st < 2 * RADIUS + 1; st++) {
        num = fmaf(w, cpp[st], num);
        den = fmaf(w, mpp[st], den);
        w *= r;
        r *= RATIO_C;
    }
    float e = num / (den + 1e-10f);
    g_eqtab[b][p] = e;
    if (p == TABN - 1) g_eqtab[b][TABN] = e;   // guard duplicate
}

__device__ __forceinline__ float eq_lerp_s(float xraw, float mn, float inv,
                                           const float* __restrict__ tb) {
    float v = (xraw - mn) * inv;
    float t = v * (float)(TABN - 1);
    int i0 = (int)t;
    float f = t - (float)i0;
    float e0 = tb[i0];
    float e1 = tb[i0 + 1];
    return fmaf(f, e1 - e0, e0);
}

// 256 blocks x 256 threads; 16KB table in smem; 2 out px/thread; re-zero g_mom.
__global__ void __launch_bounds__(256)
k_out(const float* __restrict__ x, float* __restrict__ out) {
    __shared__ float tab[TABN + 1];     // 16.4KB
    const int t = threadIdx.x;
    const int b = blockIdx.x >> 7;      // 128 blocks per batch
    const int sl = blockIdx.x & 127;

    // re-zero g_mom for the next replay (convtable already consumed it)
    if (blockIdx.x < 16) ((float*)g_mom)[blockIdx.x * 256 + t] = 0.0f;

    // hoist input loads above staging
    int local = 2 * t;                   // 0..510
    int oy = sl * 2 + (local >> 8);      // block covers 2 output rows
    int ox = local & 255;                // even
    const float* base = x + b * NPIX;
    float4 r0 = *(const float4*)(base + (2 * oy)     * HW + 2 * ox);
    float4 r1 = *(const float4*)(base + (2 * oy + 1) * HW + 2 * ox);

    {
        const float4* src = (const float4*)g_eqtab[b];
        float4* dst4 = (float4*)tab;
        #pragma unroll
        for (int q = 0; q < 4; q++) dst4[q * 256 + t] = src[q * 256 + t];
        if (t == 0) tab[TABN] = tab[TABN - 1];   // guard for v == 1.0
    }
    __syncthreads();

    const float mn  = g_scale[0];
    const float inv = g_scale[1];

    float e0 = eq_lerp_s(r0.x, mn, inv, tab) + eq_lerp_s(r0.y, mn, inv, tab)
             + eq_lerp_s(r1.x, mn, inv, tab) + eq_lerp_s(r1.y, mn, inv, tab);
    float e1 = eq_lerp_s(r0.z, mn, inv, tab) + eq_lerp_s(r0.w, mn, inv, tab)
             + eq_lerp_s(r1.z, mn, inv, tab) + eq_lerp_s(r1.w, mn, inv, tab);

    float2 o2;
    o2.x = (0.25f * e0 - 0.15f) / 0.1f;
    o2.y = (0.25f * e1 - 0.15f) / 0.1f;
    *(float2*)(out + b * 65536 + oy * 256 + ox) = o2;
}

extern "C" void kernel_launch(void* const* d_in, const int* in_sizes, int n_in,
                              void* d_out, int out_size) {
    const float* x = (const float*)d_in[0];
    float* out = (float*)d_out;
    k_hist<<<dim3(64, 2), 512>>>(x);
    k_convtable<<<dim3(8, 2), 512>>>();
    k_out<<<256, 256>>>(x, out);
}

// round 17
// speedup vs baseline: 1.0105x; 1.0105x over previous
#include <cuda_runtime.h>

// XrayTransforms: standardize -> soft-hist equalize -> 2x bilinear (=2x2 avg) -> normalize
// x: (2,1,512,512) f32, out: (2,1,256,256) f32
//
// Round 17: TWO kernels.
//   k_hist  : minmax partials + fixed-grid fine hist of raw x (2048 bins),
//             atomic flush to g_mom (counts exact in f32)
//   k_fused : per block (128 blocks x 512 thr): stage g_mom window + minmax
//             reduce; runtime-grid Gaussian conv (256 bins); scan -> cdfn;
//             build 2048-entry eq table in smem; output 2 px/thread.
//             Block 0 re-zeroes g_mom after a completion-counter handshake
//             (replay-safe; device globals zero-init).

#define NB 256
#define HW 512
#define NPIX (HW*HW)            // 262144 per batch
#define SUBN 2048
#define TABN 2048
#define RADIUS 12
#define TWO_A_D  39.21568627450980f   // 2*A*Delta (Delta = 1/255), A = 5000
#define A_D2     0.07689350249903883f // A*Delta^2
#define RATIO_C  0.85745500f          // exp(-2*A*Delta^2)
#define INV255   (1.0f/255.0f)
#define LPAD 128
#define PWIN 2336               // 128 + 2048 + 160
#define PAD (NB + 2*RADIUS)     // 280

__device__ float g_pmin[128];
__device__ float g_pmax[128];
__device__ float g_mom[2][SUBN];   // fine hist of raw x (atomic-accumulated)
__device__ int   g_cnt;            // staging completion counter (returns to 0)

// grid (64,2) x 512: one input pass: minmax partials + fixed-grid binning.
__global__ void __launch_bounds__(512)
k_hist(const float* __restrict__ x) {
    __shared__ float sh[SUBN];                 // 8KB
    __shared__ float smn[512], smx[512];       // 4KB
    const int t = threadIdx.x;
    const int b = blockIdx.y;

    for (int i = t; i < SUBN; i += 512) sh[i] = 0.0f;

    const float4* xb = (const float4*)(x + b * NPIX) + blockIdx.x * 1024;
    float4 p0 = xb[t];
    float4 p1 = xb[512 + t];
    __syncthreads();

    float mn = fminf(fminf(p0.x, p0.y), fminf(p0.z, p0.w));
    float mx = fmaxf(fmaxf(p0.x, p0.y), fmaxf(p0.z, p0.w));
    mn = fminf(mn, fminf(fminf(p1.x, p1.y), fminf(p1.z, p1.w)));
    mx = fmaxf(mx, fmaxf(fmaxf(p1.x, p1.y), fmaxf(p1.z, p1.w)));
    smn[t] = mn; smx[t] = mx;

    // fixed-grid binning: bin i = floor(x*2048), centers (i+0.5)/2048
    float vv[8] = {p0.x, p0.y, p0.z, p0.w, p1.x, p1.y, p1.z, p1.w};
    #pragma unroll
    for (int q = 0; q < 8; q++) {
        int i = (int)(vv[q] * 2048.0f);
        i = min(max(i, 0), SUBN - 1);
        atomicAdd(&sh[i], 1.0f);
    }
    __syncthreads();

    for (int o = 256; o; o >>= 1) {
        if (t < o) {
            smn[t] = fminf(smn[t], smn[t + o]);
            smx[t] = fmaxf(smx[t], smx[t + o]);
        }
        __syncthreads();
    }
    if (t == 0) {
        int bid = b * 64 + blockIdx.x;
        g_pmin[bid] = smn[0];
        g_pmax[bid] = smx[0];
    }

    float* dst = g_mom[b];
    for (int i = t; i < SUBN; i += 512) {
        float v = sh[i];
        if (v != 0.0f) atomicAdd(&dst[i], v);
    }
}

// 128 blocks x 512 threads: everything else in one kernel.
__global__ void __launch_bounds__(512)
k_fused(const float* __restrict__ x, float* __restrict__ out) {
    __shared__ float win[PWIN];        // 9.3KB padded fine hist
    __shared__ float tab[TABN + 1];    // 8.2KB eq table
    __shared__ float SC[NB];
    __shared__ float CP[PAD];
    __shared__ float MP[PAD];
    __shared__ float smm[256];
    const int tid = threadIdx.x;       // 512 threads = 16 warps
    const int bid = blockIdx.x;
    const int b = bid >> 6;            // 64 blocks per batch
    const int sl = bid & 63;
    const int wid = tid >> 5;
    const int lane = tid & 31;

    // hoisted input loads: block covers 4 output rows, 2 out px/thread
    int local = 2 * tid;               // 0..1022
    int oy = sl * 4 + (local >> 8);
    int ox = local & 255;              // even
    const float* base = x + b * NPIX;
    float4 r0 = *(const float4*)(base + (2 * oy)     * HW + 2 * ox);
    float4 r1 = *(const float4*)(base + (2 * oy + 1) * HW + 2 * ox);

    // stage minmax partials + padded conv window
    if (tid < 128) smm[tid] = g_pmin[tid];
    else if (tid < 256) smm[tid] = g_pmax[tid - 128];
    for (int i = tid; i < PWIN; i += 512) {
        int gi = i - LPAD;
        win[i] = (gi >= 0 && gi < SUBN) ? g_mom[b][gi] : 0.0f;
    }
    if (tid < PAD) { CP[tid] = 0.0f; MP[tid] = 0.0f; }
    __syncthreads();

    // signal: this block's staging of g_mom is complete
    if (tid == 0) atomicAdd(&g_cnt, 1);

    // minmax reduce (min in smm[0:128], max in smm[128:256])
    for (int o = 64; o; o >>= 1) {
        if (tid < o) smm[tid] = fminf(smm[tid], smm[tid + o]);
        else if (tid >= 128 && tid < 128 + o) smm[tid] = fmaxf(smm[tid], smm[tid + o]);
        __syncthreads();
    }
    const float mn    = smm[0];
    const float range = smm[128] - smm[0] + 1e-6f;
    const float inv   = 1.0f / range;
    const float s     = inv * (1.0f / 2048.0f);   // v-spacing of fine bins
    const float dlt   = 32.0f * s;
    const float rstep = __expf(-10000.0f * dlt * dlt);

    // conv: warp per bin; lane taps m = lane-127 + 32*it, 8 taps
    #pragma unroll
    for (int jj = 0; jj < 16; jj++) {
        const int j = wid * 16 + jj;                 // bin 0..255
        float bj = (float)j * INV255;
        float icen = (bj * range + mn) * 2048.0f - 0.5f;
        int i0 = __float2int_rn(icen);
        float d0 = ((float)i0 - icen + (float)(lane - 127)) * s;
        float w = __expf(-5000.0f * d0 * d0);
        float r = __expf(-5000.0f * (2.0f * d0 * dlt + dlt * dlt));
        const float* p = win + LPAD + i0 + (lane - 127);
        float h = 0.0f;
        #pragma unroll
        for (int it = 0; it < 8; it++) {
            h += w * p[it * 32];
            w *= r;
            r *= rstep;
        }
        #pragma unroll
        for (int o = 16; o; o >>= 1) h += __shfl_xor_sync(0xFFFFFFFFu, h, o);
        if (lane == 0) SC[j] = h;
    }
    __syncthreads();

    // scan -> padded cdfn
    #pragma unroll
    for (int o = 1; o < NB; o <<= 1) {
        float add = (tid < NB && tid >= o) ? SC[tid - o] : 0.0f;
        __syncthreads();
        if (tid < NB) SC[tid] += add;
        __syncthreads();
    }
    if (tid < NB) {
        float total = SC[NB - 1];
        float invS  = 1.0f / (total + 1e-10f);
        float cdf   = SC[tid] * invS;
        float cdf0  = SC[0] * invS;
        CP[tid + RADIUS] = (cdf - cdf0) / (1.0f - cdf0 + 1e-10f);
        MP[tid + RADIUS] = 1.0f;
    }
    __syncthreads();

    // build 2048-entry eq table, 4 entries/thread
    #pragma unroll
    for (int q = 0; q < 4; q++) {
        int p = q * 512 + tid;          // 0..2047
        float v = (float)p * (1.0f / (float)(TABN - 1));
        int k = __float2int_rn(v * 255.0f);
        int jlo = k - RADIUS;
        float d0 = v - (float)jlo * INV255;
        float w = __expf(-5000.0f * d0 * d0);
        float r = __expf(TWO_A_D * d0 - A_D2);
        const float* cpp = CP + jlo + RADIUS;
        const float* mpp = MP + jlo + RADIUS;
        float num = 0.0f, den = 0.0f;
        #pragma unroll
        for (int st = 0; st < 2 * RADIUS + 1; st++) {
            num = fmaf(w, cpp[st], num);
            den = fmaf(w, mpp[st], den);
            w *= r;
            r *= RATIO_C;
        }
        float e = num / (den + 1e-10f);
        tab[p] = e;
        if (p == TABN - 1) tab[TABN] = e;   // guard for v == 1.0
    }
    __syncthreads();

    // output
    {
        float v, t2, f; int i0;
        float e0, e1, acc0 = 0.0f, acc1 = 0.0f;
        float px0[4] = {r0.x, r0.y, r1.x, r1.y};
        float px1[4] = {r0.z, r0.w, r1.z, r1.w};
        #pragma unroll
        for (int q = 0; q < 4; q++) {
            v = (px0[q] - mn) * inv;  t2 = v * (float)(TABN - 1);
            i0 = (int)t2; f = t2 - (float)i0;
            e0 = tab[i0]; e1 = tab[i0 + 1];
            acc0 += fmaf(f, e1 - e0, e0);
            v = (px1[q] - mn) * inv;  t2 = v * (float)(TABN - 1);
            i0 = (int)t2; f = t2 - (float)i0;
            e0 = tab[i0]; e1 = tab[i0 + 1];
            acc1 += fmaf(f, e1 - e0, e0);
        }
        float2 o2;
        o2.x = (0.25f * acc0 - 0.15f) / 0.1f;
        o2.y = (0.25f * acc1 - 0.15f) / 0.1f;
        *(float2*)(out + b * 65536 + oy * 256 + ox) = o2;
    }

    // block 0: wait for all stagings (long since done), reset counter, zero g_mom
    if (bid == 0) {
        if (tid == 0) {
            while (atomicAdd(&g_cnt, 0) < 128) __nanosleep(32);
            atomicExch(&g_cnt, 0);
        }
        __syncthreads();
        for (int i = tid; i < 2 * SUBN; i += 512)
            ((float*)g_mom)[i] = 0.0f;
    }
}

extern "C" void kernel_launch(void* const* d_in, const int* in_sizes, int n_in,
                              void* d_out, int out_size) {
    const float* x = (const float*)d_in[0];
    float* out = (float*)d_out;
    k_hist<<<dim3(64, 2), 512>>>(x);
    k_fused<<<128, 512>>>(x, out);
}